// round 1
// baseline (speedup 1.0000x reference)
#include <cuda_runtime.h>
#include <math.h>

#define NT 131072
#define ET 2097152
#define NP 24576
#define EP 196608
#define D_IN 480
#define HID 128
#define NHEAD 4
#define CDIM 32
#define NLAYERS 3
#define BATCH 2048
#define LN_EPS 1e-5f

// ---------------- scratch (device globals; no allocations allowed) ----------------
__device__ float g_h[(size_t)NT * HID];     // current node features
__device__ float g_hp[(size_t)NT * HID];    // projected features (per layer)
__device__ float g_gat[(size_t)NT * HID];   // GAT aggregation output
__device__ float g_ssrc[NT * NHEAD];
__device__ float g_sdst[NT * NHEAD];
__device__ int   g_rowptr[NT + 1];
__device__ int   g_cursor[NT];              // also used as degree histogram
__device__ int   g_srcsorted[ET + NT];
__device__ float g_pool[2 * BATCH * HID];
__device__ float g_cnt[2 * BATCH];

// ---------------- CSR build ----------------
__global__ void k_hist(const int* __restrict__ dst, int* __restrict__ deg, int E) {
    int i = blockIdx.x * blockDim.x + threadIdx.x;
    if (i < E) atomicAdd(&deg[dst[i]], 1);
}

// single-block exclusive scan of (deg[i] + 1) over n entries -> rowptr
__global__ void k_scan(const int* __restrict__ deg, int* __restrict__ rowptr, int n) {
    __shared__ int ss[1024];
    int tid = threadIdx.x;
    int chunk = (n + 1023) >> 10;
    int s = tid * chunk;
    int e = min(s + chunk, n);
    int local = 0;
    for (int i = s; i < e; i++) local += deg[i] + 1;
    ss[tid] = local;
    __syncthreads();
    for (int d = 1; d < 1024; d <<= 1) {
        int t = (tid >= d) ? ss[tid - d] : 0;
        __syncthreads();
        ss[tid] += t;
        __syncthreads();
    }
    int run = ss[tid] - local; // exclusive prefix
    for (int i = s; i < e; i++) { rowptr[i] = run; run += deg[i] + 1; }
    if (tid == 0) rowptr[n] = ss[1023];
}

__global__ void k_scatter(const int* __restrict__ src, const int* __restrict__ dst,
                          const int* __restrict__ rowptr, int* __restrict__ cursor,
                          int* __restrict__ outsrc, int E, int N) {
    int i = blockIdx.x * blockDim.x + threadIdx.x;
    if (i >= E + N) return;
    int s, d;
    if (i < E) { s = src[i]; d = dst[i]; }
    else       { s = d = i - E; }         // self loops
    int pos = rowptr[d] + atomicAdd(&cursor[d], 1);
    outsrc[pos] = s;
}

// ---------------- SGEMM: C[M,128] = act(A[M,K] @ W[K,128] + bias) ----------------
// MODE 0: no bias/act.  MODE 1: relu(.+bias)
template <int MODE>
__global__ void __launch_bounds__(256) k_gemm(const float* __restrict__ A,
                                              const float* __restrict__ W,
                                              const float* __restrict__ bias,
                                              float* __restrict__ C, int K) {
    __shared__ float As[16][129]; // [k][m], padded (conflict-free stores)
    __shared__ float Bs[16][128]; // [k][n]
    int tid = threadIdx.x;
    int m0 = blockIdx.x * 128;
    int ty = tid >> 4;   // 0..15
    int tx = tid & 15;   // 0..15
    int acol = tid & 15; // A load: k within tile
    int arow = tid >> 4; // A load: base row
    int brow = tid >> 7; // 0..1
    int bcol = tid & 127;

    float acc[8][8];
#pragma unroll
    for (int i = 0; i < 8; i++)
#pragma unroll
        for (int j = 0; j < 8; j++) acc[i][j] = 0.f;

    for (int k0 = 0; k0 < K; k0 += 16) {
#pragma unroll
        for (int i = 0; i < 8; i++) {
            int r = arow + (i << 4);
            As[acol][r] = A[(size_t)(m0 + r) * K + k0 + acol];
        }
#pragma unroll
        for (int i = 0; i < 8; i++) {
            int r = brow + (i << 1);
            Bs[r][bcol] = W[(size_t)(k0 + r) * 128 + bcol];
        }
        __syncthreads();
#pragma unroll
        for (int kk = 0; kk < 16; kk++) {
            float a[8], b[8];
#pragma unroll
            for (int i = 0; i < 8; i++) a[i] = As[kk][ty + (i << 4)];
#pragma unroll
            for (int j = 0; j < 8; j++) b[j] = Bs[kk][tx + (j << 4)];
#pragma unroll
            for (int i = 0; i < 8; i++)
#pragma unroll
                for (int j = 0; j < 8; j++) acc[i][j] = fmaf(a[i], b[j], acc[i][j]);
        }
        __syncthreads();
    }

#pragma unroll
    for (int i = 0; i < 8; i++) {
        int rm = m0 + ty + (i << 4);
#pragma unroll
        for (int j = 0; j < 8; j++) {
            int cn = tx + (j << 4);
            float v = acc[i][j];
            if (MODE == 1) v = fmaxf(v + bias[cn], 0.f);
            C[(size_t)rm * 128 + cn] = v;
        }
    }
}

// ---------------- attention scores: s_src/s_dst per (node, head) ----------------
__global__ void k_scores(const float* __restrict__ hp, const float* __restrict__ asrc,
                         const float* __restrict__ adst, float* __restrict__ ssrc,
                         float* __restrict__ sdst, int N) {
    int gw = (blockIdx.x * blockDim.x + threadIdx.x) >> 5;
    int lane = threadIdx.x & 31;
    if (gw >= N * NHEAD) return;
    int n = gw >> 2, hh = gw & 3;
    float v = hp[(size_t)n * HID + hh * CDIM + lane];
    float a = v * asrc[hh * CDIM + lane];
    float b = v * adst[hh * CDIM + lane];
#pragma unroll
    for (int o = 16; o; o >>= 1) {
        a += __shfl_down_sync(0xffffffffu, a, o);
        b += __shfl_down_sync(0xffffffffu, b, o);
    }
    if (lane == 0) { ssrc[n * 4 + hh] = a; sdst[n * 4 + hh] = b; }
}

// ---------------- fused softmax + aggregate: one warp per (node, head) ----------------
__global__ void k_aggregate(const float* __restrict__ hp, const float* __restrict__ ssrc,
                            const float* __restrict__ sdst, const int* __restrict__ rowptr,
                            const int* __restrict__ srcs, const float* __restrict__ bias,
                            float* __restrict__ out, int N) {
    int gw = (blockIdx.x * blockDim.x + threadIdx.x) >> 5;
    int lane = threadIdx.x & 31;
    if (gw >= N * NHEAD) return;
    int n = gw >> 2, hh = gw & 3;
    float sd = sdst[n * 4 + hh];
    int e0 = rowptr[n], e1 = rowptr[n + 1];
    float m = -1e30f, z = 0.f, acc = 0.f;
    for (int e = e0; e < e1; e++) {
        int s = srcs[e];
        float ev = ssrc[s * 4 + hh] + sd;
        ev = (ev > 0.f) ? ev : 0.2f * ev;         // leaky_relu 0.2
        if (ev > m) {                              // online softmax rescale
            float c = __expf(m - ev);
            z *= c; acc *= c; m = ev;
        }
        float p = __expf(ev - m);
        float hv = hp[(size_t)s * HID + hh * CDIM + lane];
        z += p;
        acc = fmaf(p, hv, acc);
    }
    out[(size_t)n * HID + hh * CDIM + lane] = acc / z + bias[hh * CDIM + lane];
}

// ---------------- layernorm + relu + residual (in place on h) ----------------
__global__ void k_lnres(const float* __restrict__ x, const float* __restrict__ gam,
                        const float* __restrict__ bet, float* __restrict__ h, int N) {
    int gw = (blockIdx.x * blockDim.x + threadIdx.x) >> 5;
    int lane = threadIdx.x & 31;
    if (gw >= N) return;
    const float* row = x + (size_t)gw * HID;
    float v[4];
    float s = 0.f;
#pragma unroll
    for (int t = 0; t < 4; t++) { v[t] = row[lane + 32 * t]; s += v[t]; }
#pragma unroll
    for (int o = 16; o; o >>= 1) s += __shfl_xor_sync(0xffffffffu, s, o);
    float mu = s * (1.f / 128.f);
    float var = 0.f;
#pragma unroll
    for (int t = 0; t < 4; t++) { float d = v[t] - mu; var = fmaf(d, d, var); }
#pragma unroll
    for (int o = 16; o; o >>= 1) var += __shfl_xor_sync(0xffffffffu, var, o);
    var *= (1.f / 128.f);
    float inv = rsqrtf(var + LN_EPS);
#pragma unroll
    for (int t = 0; t < 4; t++) {
        int c = lane + 32 * t;
        float y = (v[t] - mu) * inv * gam[c] + bet[c];
        y = fmaxf(y, 0.f);
        h[(size_t)gw * HID + c] += y;  // residual: h_new = relu(LN(out)) + h_old
    }
}

// ---------------- mean pool by batch ----------------
__global__ void k_pool(const float* __restrict__ h, const int* __restrict__ batch,
                       float* __restrict__ pool, float* __restrict__ cnt, int N) {
    int gw = (blockIdx.x * blockDim.x + threadIdx.x) >> 5;
    int lane = threadIdx.x & 31;
    if (gw >= N) return;
    int b = batch[gw];
#pragma unroll
    for (int t = 0; t < 4; t++) {
        int c = lane + 32 * t;
        atomicAdd(&pool[(size_t)b * HID + c], h[(size_t)gw * HID + c]);
    }
    if (lane == 0) atomicAdd(&cnt[b], 1.f);
}

// ---------------- MLP head: one block per batch row ----------------
__global__ void __launch_bounds__(128) k_mlp(const float* __restrict__ poolA, const float* __restrict__ cntA,
                                             const float* __restrict__ poolB, const float* __restrict__ cntB,
                                             const float* __restrict__ Wc1, const float* __restrict__ bc1,
                                             const float* __restrict__ Wc2, const float* __restrict__ bc2,
                                             const float* __restrict__ Wc3, const float* __restrict__ bc3,
                                             float* __restrict__ out) {
    __shared__ float z[256];
    __shared__ float o1[128];
    __shared__ float o2[64];
    int b = blockIdx.x, t = threadIdx.x;
    float ca = fmaxf(cntA[b], 1.f), cb = fmaxf(cntB[b], 1.f);
    z[t]       = poolA[(size_t)b * HID + t] / ca;
    z[t + 128] = poolB[(size_t)b * HID + t] / cb;
    __syncthreads();
    float a1 = bc1[t];
#pragma unroll 8
    for (int i = 0; i < 256; i++) a1 = fmaf(z[i], Wc1[i * 128 + t], a1);
    o1[t] = fmaxf(a1, 0.f);
    __syncthreads();
    if (t < 64) {
        float a2 = bc2[t];
#pragma unroll 8
        for (int i = 0; i < 128; i++) a2 = fmaf(o1[i], Wc2[i * 64 + t], a2);
        o2[t] = fmaxf(a2, 0.f);
    }
    __syncthreads();
    if (t < 32) {
        float a3 = fmaf(o2[t], Wc3[t], o2[t + 32] * Wc3[t + 32]);
#pragma unroll
        for (int o = 16; o; o >>= 1) a3 += __shfl_xor_sync(0xffffffffu, a3, o);
        if (t == 0) out[b] = 1.f / (1.f + __expf(-(a3 + bc3[0])));
    }
}

// ---------------- host orchestration ----------------
static void encode_graph(const float* x, const int* ei, int N, int E,
                         const float* W_in, const float* b_in,
                         const float* Wg, const float* bg,
                         const float* att_src, const float* att_dst,
                         const float* ln_g, const float* ln_b,
                         float* hB, float* hpB, float* gatB,
                         float* ssrcB, float* sdstB,
                         int* rpB, int* curB, int* ssB) {
    const int* src = ei;
    const int* dst = ei + E;

    // CSR build (dst-sorted, self loops included)
    cudaMemsetAsync(curB, 0, (size_t)N * sizeof(int));
    k_hist<<<(E + 255) / 256, 256>>>(dst, curB, E);
    k_scan<<<1, 1024>>>(curB, rpB, N);
    cudaMemsetAsync(curB, 0, (size_t)N * sizeof(int));
    k_scatter<<<(E + N + 255) / 256, 256>>>(src, dst, rpB, curB, ssB, E, N);

    // h = relu(x @ W_in + b_in)
    k_gemm<1><<<N / 128, 256>>>(x, W_in, b_in, hB, D_IN);

    for (int l = 0; l < NLAYERS; l++) {
        k_gemm<0><<<N / 128, 256>>>(hB, Wg + (size_t)l * HID * HID, nullptr, hpB, HID);
        k_scores<<<(N * NHEAD) / 8, 256>>>(hpB, att_src + l * HID, att_dst + l * HID,
                                           ssrcB, sdstB, N);
        k_aggregate<<<(N * NHEAD) / 8, 256>>>(hpB, ssrcB, sdstB, rpB, ssB,
                                              bg + l * HID, gatB, N);
        k_lnres<<<N / 8, 256>>>(gatB, ln_g + l * HID, ln_b + l * HID, hB, N);
    }
}

extern "C" void kernel_launch(void* const* d_in, const int* in_sizes, int n_in,
                              void* d_out, int out_size) {
    const float* tcr_x    = (const float*)d_in[0];
    const int*   tcr_ei   = (const int*)d_in[1];
    const int*   tcr_bat  = (const int*)d_in[2];
    const float* pep_x    = (const float*)d_in[3];
    const int*   pep_ei   = (const int*)d_in[4];
    const int*   pep_bat  = (const int*)d_in[5];
    const float* W_in     = (const float*)d_in[6];
    const float* b_in     = (const float*)d_in[7];
    const float* Wg       = (const float*)d_in[8];
    const float* bg       = (const float*)d_in[9];
    const float* att_src  = (const float*)d_in[10];
    const float* att_dst  = (const float*)d_in[11];
    const float* ln_g     = (const float*)d_in[12];
    const float* ln_b     = (const float*)d_in[13];
    const float* Wc1      = (const float*)d_in[14];
    const float* bc1      = (const float*)d_in[15];
    const float* Wc2      = (const float*)d_in[16];
    const float* bc2      = (const float*)d_in[17];
    const float* Wc3      = (const float*)d_in[18];
    const float* bc3      = (const float*)d_in[19];
    float* out = (float*)d_out;

    int Ntc = in_sizes[2];          // 131072
    int Etc = in_sizes[1] / 2;      // 2097152
    int Npp = in_sizes[5];          // 24576
    int Epp = in_sizes[4] / 2;      // 196608

    float *hB, *hpB, *gatB, *ssrcB, *sdstB, *poolB, *cntB;
    int *rpB, *curB, *ssB;
    cudaGetSymbolAddress((void**)&hB, g_h);
    cudaGetSymbolAddress((void**)&hpB, g_hp);
    cudaGetSymbolAddress((void**)&gatB, g_gat);
    cudaGetSymbolAddress((void**)&ssrcB, g_ssrc);
    cudaGetSymbolAddress((void**)&sdstB, g_sdst);
    cudaGetSymbolAddress((void**)&rpB, g_rowptr);
    cudaGetSymbolAddress((void**)&curB, g_cursor);
    cudaGetSymbolAddress((void**)&ssB, g_srcsorted);
    cudaGetSymbolAddress((void**)&poolB, g_pool);
    cudaGetSymbolAddress((void**)&cntB, g_cnt);

    cudaMemsetAsync(poolB, 0, 2 * BATCH * HID * sizeof(float));
    cudaMemsetAsync(cntB, 0, 2 * BATCH * sizeof(float));

    // TCR tower
    encode_graph(tcr_x, tcr_ei, Ntc, Etc, W_in, b_in, Wg, bg, att_src, att_dst,
                 ln_g, ln_b, hB, hpB, gatB, ssrcB, sdstB, rpB, curB, ssB);
    k_pool<<<Ntc / 8, 256>>>(hB, tcr_bat, poolB, cntB, Ntc);

    // peptide tower (reuses scratch)
    encode_graph(pep_x, pep_ei, Npp, Epp, W_in, b_in, Wg, bg, att_src, att_dst,
                 ln_g, ln_b, hB, hpB, gatB, ssrcB, sdstB, rpB, curB, ssB);
    k_pool<<<Npp / 8, 256>>>(hB, pep_bat, poolB + BATCH * HID, cntB + BATCH, Npp);

    // MLP head
    k_mlp<<<BATCH, 128>>>(poolB, cntB, poolB + BATCH * HID, cntB + BATCH,
                          Wc1, bc1, Wc2, bc2, Wc3, bc3, out);
}

// round 2
// speedup vs baseline: 1.4914x; 1.4914x over previous
#include <cuda_runtime.h>
#include <math.h>

#define NT 131072
#define ET 2097152
#define NP 24576
#define EP 196608
#define D_IN 480
#define HID 128
#define NHEAD 4
#define CDIM 32
#define NLAYERS 3
#define BATCH 2048
#define LN_EPS 1e-5f

// ---------------- scratch (device globals; no allocations allowed) ----------------
__device__ float g_h[(size_t)NT * HID];     // current node features
__device__ float g_hp[(size_t)NT * HID];    // projected features (per layer)
__device__ float g_gat[(size_t)NT * HID];   // GAT aggregation output
__device__ float g_ssrc[NT * NHEAD];
__device__ float g_sdst[NT * NHEAD];
__device__ int   g_rowptr[NT + 1];
__device__ int   g_cursor[NT];              // also used as degree histogram
__device__ int   g_srcsorted[ET + NT];
__device__ float g_pool[2 * BATCH * HID];
__device__ float g_cnt[2 * BATCH];

// ---------------- f32x2 packed helpers (sm_103a) ----------------
__device__ __forceinline__ unsigned long long pack2(float x, float y) {
    unsigned long long r;
    asm("mov.b64 %0, {%1, %2};" : "=l"(r) : "f"(x), "f"(y));
    return r;
}
__device__ __forceinline__ float2 unpack2(unsigned long long v) {
    float2 r;
    asm("mov.b64 {%0, %1}, %2;" : "=f"(r.x), "=f"(r.y) : "l"(v));
    return r;
}
__device__ __forceinline__ void ffma2(unsigned long long& d, unsigned long long a, unsigned long long b) {
    asm("fma.rn.f32x2 %0, %1, %2, %0;" : "+l"(d) : "l"(a), "l"(b));
}

// ---------------- CSR build ----------------
__global__ void k_hist(const int* __restrict__ dst, int* __restrict__ deg, int E) {
    int i = blockIdx.x * blockDim.x + threadIdx.x;
    if (i < E) atomicAdd(&deg[dst[i]], 1);
}

// single-block exclusive scan of (deg[i] + 1) over n entries -> rowptr
__global__ void k_scan(const int* __restrict__ deg, int* __restrict__ rowptr, int n) {
    __shared__ int ss[1024];
    int tid = threadIdx.x;
    int chunk = (n + 1023) >> 10;
    int s = tid * chunk;
    int e = min(s + chunk, n);
    int local = 0;
    for (int i = s; i < e; i++) local += deg[i] + 1;
    ss[tid] = local;
    __syncthreads();
    for (int d = 1; d < 1024; d <<= 1) {
        int t = (tid >= d) ? ss[tid - d] : 0;
        __syncthreads();
        ss[tid] += t;
        __syncthreads();
    }
    int run = ss[tid] - local; // exclusive prefix
    for (int i = s; i < e; i++) { rowptr[i] = run; run += deg[i] + 1; }
    if (tid == 0) rowptr[n] = ss[1023];
}

__global__ void k_scatter(const int* __restrict__ src, const int* __restrict__ dst,
                          const int* __restrict__ rowptr, int* __restrict__ cursor,
                          int* __restrict__ outsrc, int E, int N) {
    int i = blockIdx.x * blockDim.x + threadIdx.x;
    if (i >= E + N) return;
    int s, d;
    if (i < E) { s = src[i]; d = dst[i]; }
    else       { s = d = i - E; }         // self loops
    int pos = rowptr[d] + atomicAdd(&cursor[d], 1);
    outsrc[pos] = s;
}

// ---------------- SGEMM (f32x2): C[M,128] = act(A[M,K] @ W[K,128] + bias) ----------------
// MODE 0: no bias/act.  MODE 1: relu(.+bias)
template <int MODE>
__global__ void __launch_bounds__(256) k_gemm(const float* __restrict__ A,
                                              const float* __restrict__ W,
                                              const float* __restrict__ bias,
                                              float* __restrict__ C, int K) {
    __shared__ float As[16][129]; // [k][m], padded (conflict-free stores)
    __shared__ float Bs[16][128]; // [k][n]
    int tid = threadIdx.x;
    int m0 = blockIdx.x * 128;
    int ty = tid >> 4;   // 0..15 -> rows ty + 16i
    int tx = tid & 15;   // 0..15 -> col pairs {2tx, 2tx+1} + 32j
    int acol = tid & 15; // A load: k within tile
    int arow = tid >> 4; // A load: base row
    int brow = tid >> 7; // 0..1
    int bcol = tid & 127;

    unsigned long long accd[8][4];
#pragma unroll
    for (int i = 0; i < 8; i++)
#pragma unroll
        for (int j = 0; j < 4; j++) accd[i][j] = 0ULL;

    for (int k0 = 0; k0 < K; k0 += 16) {
#pragma unroll
        for (int i = 0; i < 8; i++) {
            int r = arow + (i << 4);
            As[acol][r] = A[(size_t)(m0 + r) * K + k0 + acol];
        }
#pragma unroll
        for (int i = 0; i < 8; i++) {
            int r = brow + (i << 1);
            Bs[r][bcol] = W[(size_t)(k0 + r) * 128 + bcol];
        }
        __syncthreads();
#pragma unroll
        for (int kk = 0; kk < 16; kk++) {
            unsigned long long bp[4];
            float av[8];
#pragma unroll
            for (int j = 0; j < 4; j++)
                bp[j] = *(const unsigned long long*)&Bs[kk][2 * tx + 32 * j];
#pragma unroll
            for (int i = 0; i < 8; i++) av[i] = As[kk][ty + (i << 4)];
#pragma unroll
            for (int i = 0; i < 8; i++) {
                unsigned long long ap = pack2(av[i], av[i]);
#pragma unroll
                for (int j = 0; j < 4; j++) ffma2(accd[i][j], ap, bp[j]);
            }
        }
        __syncthreads();
    }

#pragma unroll
    for (int i = 0; i < 8; i++) {
        int rm = m0 + ty + (i << 4);
#pragma unroll
        for (int j = 0; j < 4; j++) {
            int cn = 2 * tx + 32 * j;
            float2 v = unpack2(accd[i][j]);
            if (MODE == 1) {
                v.x = fmaxf(v.x + bias[cn], 0.f);
                v.y = fmaxf(v.y + bias[cn + 1], 0.f);
            }
            *(float2*)&C[(size_t)rm * 128 + cn] = v;
        }
    }
}

// ---------------- attention scores: one warp per node, all heads ----------------
__global__ void k_scores(const float* __restrict__ hp, const float* __restrict__ asrc,
                         const float* __restrict__ adst, float* __restrict__ ssrc,
                         float* __restrict__ sdst, int N) {
    int gw = (blockIdx.x * blockDim.x + threadIdx.x) >> 5;
    int lane = threadIdx.x & 31;
    if (gw >= N) return;
    int c = 4 * lane;
    int hh = lane >> 3;
    float4 v = *(const float4*)&hp[(size_t)gw * HID + c];
    float4 as = *(const float4*)&asrc[c];
    float4 ad = *(const float4*)&adst[c];
    float a = v.x * as.x + v.y * as.y + v.z * as.z + v.w * as.w;
    float b = v.x * ad.x + v.y * ad.y + v.z * ad.z + v.w * ad.w;
#pragma unroll
    for (int o = 4; o; o >>= 1) {
        a += __shfl_down_sync(0xffffffffu, a, o, 8);
        b += __shfl_down_sync(0xffffffffu, b, o, 8);
    }
    if ((lane & 7) == 0) { ssrc[gw * 4 + hh] = a; sdst[gw * 4 + hh] = b; }
}

// ---------------- fused softmax + aggregate: one warp per node, 4 heads, pipelined ----------------
__global__ void __launch_bounds__(256) k_aggregate(
        const float* __restrict__ hp, const float* __restrict__ ssrc,
        const float* __restrict__ sdst, const int* __restrict__ rowptr,
        const int* __restrict__ srcs, const float* __restrict__ bias,
        float* __restrict__ out, int N) {
    int gw = (blockIdx.x * blockDim.x + threadIdx.x) >> 5;
    int lane = threadIdx.x & 31;
    if (gw >= N) return;
    int hh = lane >> 3;                  // head of this lane's 4 columns
    float sd = __ldg(&sdst[gw * 4 + hh]);
    int e0 = rowptr[gw], e1 = rowptr[gw + 1];

    float m = -1e30f, z = 0.f;
    float4 acc = make_float4(0.f, 0.f, 0.f, 0.f);

    // 2-deep software pipeline (degree >= 1 always: self loop)
    int s_cur = __ldg(&srcs[e0]);
    float sv_cur = __ldg(&ssrc[s_cur * 4 + hh]);
    float4 hv_cur = __ldg((const float4*)(hp + (size_t)s_cur * HID + 4 * lane));

    for (int e = e0; e < e1; e++) {
        int s_nxt = s_cur;
        float sv_nxt = sv_cur;
        float4 hv_nxt = hv_cur;
        if (e + 1 < e1) {
            s_nxt = __ldg(&srcs[e + 1]);
            sv_nxt = __ldg(&ssrc[s_nxt * 4 + hh]);
            hv_nxt = __ldg((const float4*)(hp + (size_t)s_nxt * HID + 4 * lane));
        }
        float ev = sv_cur + sd;
        ev = (ev > 0.f) ? ev : 0.2f * ev;       // leaky_relu 0.2
        if (ev > m) {
            float c = __expf(m - ev);
            z *= c; acc.x *= c; acc.y *= c; acc.z *= c; acc.w *= c;
            m = ev;
        }
        float p = __expf(ev - m);
        z += p;
        acc.x = fmaf(p, hv_cur.x, acc.x);
        acc.y = fmaf(p, hv_cur.y, acc.y);
        acc.z = fmaf(p, hv_cur.z, acc.z);
        acc.w = fmaf(p, hv_cur.w, acc.w);
        s_cur = s_nxt; sv_cur = sv_nxt; hv_cur = hv_nxt;
    }
    float inv = 1.f / z;
    float4 bs = *(const float4*)&bias[4 * lane];
    float4 r;
    r.x = acc.x * inv + bs.x;
    r.y = acc.y * inv + bs.y;
    r.z = acc.z * inv + bs.z;
    r.w = acc.w * inv + bs.w;
    *(float4*)&out[(size_t)gw * HID + 4 * lane] = r;
}

// ---------------- layernorm + relu + residual (in place on h) ----------------
__global__ void k_lnres(const float* __restrict__ x, const float* __restrict__ gam,
                        const float* __restrict__ bet, float* __restrict__ h, int N) {
    int gw = (blockIdx.x * blockDim.x + threadIdx.x) >> 5;
    int lane = threadIdx.x & 31;
    if (gw >= N) return;
    const float* row = x + (size_t)gw * HID;
    float v[4];
    float s = 0.f;
#pragma unroll
    for (int t = 0; t < 4; t++) { v[t] = row[lane + 32 * t]; s += v[t]; }
#pragma unroll
    for (int o = 16; o; o >>= 1) s += __shfl_xor_sync(0xffffffffu, s, o);
    float mu = s * (1.f / 128.f);
    float var = 0.f;
#pragma unroll
    for (int t = 0; t < 4; t++) { float d = v[t] - mu; var = fmaf(d, d, var); }
#pragma unroll
    for (int o = 16; o; o >>= 1) var += __shfl_xor_sync(0xffffffffu, var, o);
    var *= (1.f / 128.f);
    float inv = rsqrtf(var + LN_EPS);
#pragma unroll
    for (int t = 0; t < 4; t++) {
        int c = lane + 32 * t;
        float y = (v[t] - mu) * inv * gam[c] + bet[c];
        y = fmaxf(y, 0.f);
        h[(size_t)gw * HID + c] += y;  // residual: h_new = relu(LN(out)) + h_old
    }
}

// ---------------- mean pool by batch ----------------
__global__ void k_pool(const float* __restrict__ h, const int* __restrict__ batch,
                       float* __restrict__ pool, float* __restrict__ cnt, int N) {
    int gw = (blockIdx.x * blockDim.x + threadIdx.x) >> 5;
    int lane = threadIdx.x & 31;
    if (gw >= N) return;
    int b = batch[gw];
#pragma unroll
    for (int t = 0; t < 4; t++) {
        int c = lane + 32 * t;
        atomicAdd(&pool[(size_t)b * HID + c], h[(size_t)gw * HID + c]);
    }
    if (lane == 0) atomicAdd(&cnt[b], 1.f);
}

// ---------------- MLP head: one block per batch row ----------------
__global__ void __launch_bounds__(128) k_mlp(const float* __restrict__ poolA, const float* __restrict__ cntA,
                                             const float* __restrict__ poolB, const float* __restrict__ cntB,
                                             const float* __restrict__ Wc1, const float* __restrict__ bc1,
                                             const float* __restrict__ Wc2, const float* __restrict__ bc2,
                                             const float* __restrict__ Wc3, const float* __restrict__ bc3,
                                             float* __restrict__ out) {
    __shared__ float z[256];
    __shared__ float o1[128];
    __shared__ float o2[64];
    int b = blockIdx.x, t = threadIdx.x;
    float ca = fmaxf(cntA[b], 1.f), cb = fmaxf(cntB[b], 1.f);
    z[t]       = poolA[(size_t)b * HID + t] / ca;
    z[t + 128] = poolB[(size_t)b * HID + t] / cb;
    __syncthreads();
    float a1 = bc1[t];
#pragma unroll 8
    for (int i = 0; i < 256; i++) a1 = fmaf(z[i], Wc1[i * 128 + t], a1);
    o1[t] = fmaxf(a1, 0.f);
    __syncthreads();
    if (t < 64) {
        float a2 = bc2[t];
#pragma unroll 8
        for (int i = 0; i < 128; i++) a2 = fmaf(o1[i], Wc2[i * 64 + t], a2);
        o2[t] = fmaxf(a2, 0.f);
    }
    __syncthreads();
    if (t < 32) {
        float a3 = fmaf(o2[t], Wc3[t], o2[t + 32] * Wc3[t + 32]);
#pragma unroll
        for (int o = 16; o; o >>= 1) a3 += __shfl_xor_sync(0xffffffffu, a3, o);
        if (t == 0) out[b] = 1.f / (1.f + __expf(-(a3 + bc3[0])));
    }
}

// ---------------- host orchestration ----------------
static void encode_graph(const float* x, const int* ei, int N, int E,
                         const float* W_in, const float* b_in,
                         const float* Wg, const float* bg,
                         const float* att_src, const float* att_dst,
                         const float* ln_g, const float* ln_b,
                         float* hB, float* hpB, float* gatB,
                         float* ssrcB, float* sdstB,
                         int* rpB, int* curB, int* ssB) {
    const int* src = ei;
    const int* dst = ei + E;

    // CSR build (dst-sorted, self loops included)
    cudaMemsetAsync(curB, 0, (size_t)N * sizeof(int));
    k_hist<<<(E + 255) / 256, 256>>>(dst, curB, E);
    k_scan<<<1, 1024>>>(curB, rpB, N);
    cudaMemsetAsync(curB, 0, (size_t)N * sizeof(int));
    k_scatter<<<(E + N + 255) / 256, 256>>>(src, dst, rpB, curB, ssB, E, N);

    // h = relu(x @ W_in + b_in)
    k_gemm<1><<<N / 128, 256>>>(x, W_in, b_in, hB, D_IN);

    for (int l = 0; l < NLAYERS; l++) {
        k_gemm<0><<<N / 128, 256>>>(hB, Wg + (size_t)l * HID * HID, nullptr, hpB, HID);
        k_scores<<<N / 8, 256>>>(hpB, att_src + l * HID, att_dst + l * HID,
                                 ssrcB, sdstB, N);
        k_aggregate<<<N / 8, 256>>>(hpB, ssrcB, sdstB, rpB, ssB,
                                    bg + l * HID, gatB, N);
        k_lnres<<<N / 8, 256>>>(gatB, ln_g + l * HID, ln_b + l * HID, hB, N);
    }
}

extern "C" void kernel_launch(void* const* d_in, const int* in_sizes, int n_in,
                              void* d_out, int out_size) {
    const float* tcr_x    = (const float*)d_in[0];
    const int*   tcr_ei   = (const int*)d_in[1];
    const int*   tcr_bat  = (const int*)d_in[2];
    const float* pep_x    = (const float*)d_in[3];
    const int*   pep_ei   = (const int*)d_in[4];
    const int*   pep_bat  = (const int*)d_in[5];
    const float* W_in     = (const float*)d_in[6];
    const float* b_in     = (const float*)d_in[7];
    const float* Wg       = (const float*)d_in[8];
    const float* bg       = (const float*)d_in[9];
    const float* att_src  = (const float*)d_in[10];
    const float* att_dst  = (const float*)d_in[11];
    const float* ln_g     = (const float*)d_in[12];
    const float* ln_b     = (const float*)d_in[13];
    const float* Wc1      = (const float*)d_in[14];
    const float* bc1      = (const float*)d_in[15];
    const float* Wc2      = (const float*)d_in[16];
    const float* bc2      = (const float*)d_in[17];
    const float* Wc3      = (const float*)d_in[18];
    const float* bc3      = (const float*)d_in[19];
    float* out = (float*)d_out;

    int Ntc = in_sizes[2];          // 131072
    int Etc = in_sizes[1] / 2;      // 2097152
    int Npp = in_sizes[5];          // 24576
    int Epp = in_sizes[4] / 2;      // 196608

    float *hB, *hpB, *gatB, *ssrcB, *sdstB, *poolB, *cntB;
    int *rpB, *curB, *ssB;
    cudaGetSymbolAddress((void**)&hB, g_h);
    cudaGetSymbolAddress((void**)&hpB, g_hp);
    cudaGetSymbolAddress((void**)&gatB, g_gat);
    cudaGetSymbolAddress((void**)&ssrcB, g_ssrc);
    cudaGetSymbolAddress((void**)&sdstB, g_sdst);
    cudaGetSymbolAddress((void**)&rpB, g_rowptr);
    cudaGetSymbolAddress((void**)&curB, g_cursor);
    cudaGetSymbolAddress((void**)&ssB, g_srcsorted);
    cudaGetSymbolAddress((void**)&poolB, g_pool);
    cudaGetSymbolAddress((void**)&cntB, g_cnt);

    cudaMemsetAsync(poolB, 0, 2 * BATCH * HID * sizeof(float));
    cudaMemsetAsync(cntB, 0, 2 * BATCH * sizeof(float));

    // TCR tower
    encode_graph(tcr_x, tcr_ei, Ntc, Etc, W_in, b_in, Wg, bg, att_src, att_dst,
                 ln_g, ln_b, hB, hpB, gatB, ssrcB, sdstB, rpB, curB, ssB);
    k_pool<<<Ntc / 8, 256>>>(hB, tcr_bat, poolB, cntB, Ntc);

    // peptide tower (reuses scratch)
    encode_graph(pep_x, pep_ei, Npp, Epp, W_in, b_in, Wg, bg, att_src, att_dst,
                 ln_g, ln_b, hB, hpB, gatB, ssrcB, sdstB, rpB, curB, ssB);
    k_pool<<<Npp / 8, 256>>>(hB, pep_bat, poolB + BATCH * HID, cntB + BATCH, Npp);

    // MLP head
    k_mlp<<<BATCH, 128>>>(poolB, cntB, poolB + BATCH * HID, cntB + BATCH,
                          Wc1, bc1, Wc2, bc2, Wc3, bc3, out);
}